// round 2
// baseline (speedup 1.0000x reference)
#include <cuda_runtime.h>
#include <mma.h>

#define N_TOK 131072
#define DIM   512
#define MEM   25
#define ALPHA 0.2f
#define MOM   0.8f

using namespace nvcuda;

// ---------------- scratch (device globals; no allocation) ----------------
__device__ float    g_p[(size_t)N_TOK * MEM];      // softmax attention weights
__device__ float    g_W1T[DIM * DIM];              // W1 transposed [k][o]
__device__ float    g_ACW2[MEM * DIM];             // ALPHA * cache @ W2^T
__device__ int      g_assign[N_TOK];
__device__ float    g_sval[N_TOK];
__device__ float    g_rinv[N_TOK];
__device__ unsigned g_colmax[MEM];                 // ordered-uint float max
__device__ float    g_segp[(size_t)148 * MEM * DIM];
__device__ float    g_cntp[148 * MEM];
__device__ float    g_losspart[1024];

__device__ __forceinline__ unsigned f2o(float f) {
    unsigned u = __float_as_uint(f);
    return (u & 0x80000000u) ? ~u : (u | 0x80000000u);
}
__device__ __forceinline__ float o2f(unsigned u) {
    return __uint_as_float((u & 0x80000000u) ? (u & 0x7FFFFFFFu) : ~u);
}
__device__ __forceinline__ float wredsum(float v) {
    v += __shfl_xor_sync(0xffffffffu, v, 16);
    v += __shfl_xor_sync(0xffffffffu, v, 8);
    v += __shfl_xor_sync(0xffffffffu, v, 4);
    v += __shfl_xor_sync(0xffffffffu, v, 2);
    v += __shfl_xor_sync(0xffffffffu, v, 1);
    return v;
}

// ---------------- init: zero column-max ----------------
__global__ void k_init() {
    if (threadIdx.x < MEM) g_colmax[threadIdx.x] = 0u;
}

// ---------------- W1 transpose: g_W1T[k*512+o] = W[o*1024+k] ----------------
__global__ void k_transpose(const float* __restrict__ W) {
    __shared__ float t[32][33];
    int bx = blockIdx.x, by = blockIdx.y;
    int tx = threadIdx.x, ty = threadIdx.y;   // (32,8)
    #pragma unroll
    for (int yy = 0; yy < 32; yy += 8) {
        int o = by * 32 + ty + yy, k = bx * 32 + tx;
        t[ty + yy][tx] = W[(size_t)o * 1024 + k];
    }
    __syncthreads();
    #pragma unroll
    for (int yy = 0; yy < 32; yy += 8) {
        int k = bx * 32 + ty + yy, o = by * 32 + tx;
        g_W1T[(size_t)k * 512 + o] = t[tx][ty + yy];
    }
}

// ---------------- ACW2[m][o] = ALPHA * sum_k cache[m][k] * W[o][512+k] ----------------
__global__ void k_acw2(const float* __restrict__ W, const float* __restrict__ cache) {
    __shared__ float cs[DIM];
    int m = blockIdx.x;
    for (int id = threadIdx.x; id < DIM; id += blockDim.x) cs[id] = cache[m * DIM + id];
    __syncthreads();
    int lane = threadIdx.x & 31, wid = threadIdx.x >> 5;
    for (int j = wid * 64; j < wid * 64 + 64; j++) {
        float d = 0.f;
        #pragma unroll
        for (int t = 0; t < 16; t++) {
            int k = lane + 32 * t;
            d += cs[k] * W[(size_t)j * 1024 + 512 + k];
        }
        d = wredsum(d);
        if (lane == 0) g_ACW2[m * DIM + j] = ALPHA * d;
    }
}

// ---------------- text attention: p = softmax(normalize(text) @ cache^T) ----------------
__global__ void k_text_attn(const float* __restrict__ text, const float* __restrict__ cache) {
    extern __shared__ float cs[];                      // 25*512 floats
    for (int i = threadIdx.x; i < MEM * DIM / 4; i += blockDim.x)
        ((float4*)cs)[i] = ((const float4*)cache)[i];
    __syncthreads();
    int lane = threadIdx.x & 31, wid = threadIdx.x >> 5;
    int gw = blockIdx.x * (blockDim.x >> 5) + wid;
    int nw = gridDim.x * (blockDim.x >> 5);
    const float4* c4 = (const float4*)cs;
    for (int i = gw; i < N_TOK; i += nw) {
        const float4* r4 = (const float4*)(text + (size_t)i * DIM);
        float4 x[4]; float ss = 0.f;
        #pragma unroll
        for (int t = 0; t < 4; t++) {
            x[t] = r4[lane + 32 * t];
            ss += x[t].x * x[t].x + x[t].y * x[t].y + x[t].z * x[t].z + x[t].w * x[t].w;
        }
        ss = wredsum(ss);
        float rinv = rsqrtf(ss);
        float smax = -1e30f, mine = -1e30f;
        #pragma unroll
        for (int m = 0; m < MEM; m++) {
            float d = 0.f;
            #pragma unroll
            for (int t = 0; t < 4; t++) {
                float4 cc = c4[m * 128 + lane + 32 * t];
                d += x[t].x * cc.x + x[t].y * cc.y + x[t].z * cc.z + x[t].w * cc.w;
            }
            d = wredsum(d) * rinv;
            smax = fmaxf(smax, d);
            if (lane == m) mine = d;
        }
        float pm = (lane < MEM) ? expf(mine - smax) : 0.f;
        float psum = wredsum(pm);
        if (lane < MEM) g_p[(size_t)i * MEM + lane] = pm / psum;
    }
}

// ---------------- image attention: rinv, argmax slot, s value, column maxes ----------------
__global__ void k_img_attn(const float* __restrict__ img, const float* __restrict__ cache) {
    extern __shared__ float cs[];
    __shared__ unsigned cm_s[MEM];
    if (threadIdx.x < MEM) cm_s[threadIdx.x] = 0u;
    for (int i = threadIdx.x; i < MEM * DIM / 4; i += blockDim.x)
        ((float4*)cs)[i] = ((const float4*)cache)[i];
    __syncthreads();
    int lane = threadIdx.x & 31, wid = threadIdx.x >> 5;
    int gw = blockIdx.x * (blockDim.x >> 5) + wid;
    int nw = gridDim.x * (blockDim.x >> 5);
    const float4* c4 = (const float4*)cs;
    float cm[MEM];
    #pragma unroll
    for (int m = 0; m < MEM; m++) cm[m] = -1e30f;
    for (int i = gw; i < N_TOK; i += nw) {
        const float4* r4 = (const float4*)(img + (size_t)i * DIM);
        float4 x[4]; float ss = 0.f;
        #pragma unroll
        for (int t = 0; t < 4; t++) {
            x[t] = r4[lane + 32 * t];
            ss += x[t].x * x[t].x + x[t].y * x[t].y + x[t].z * x[t].z + x[t].w * x[t].w;
        }
        ss = wredsum(ss);
        float rinv = rsqrtf(ss);
        if (lane == 0) g_rinv[i] = rinv;
        float best = -1e30f; int bi = 0;
        #pragma unroll
        for (int m = 0; m < MEM; m++) {
            float d = 0.f;
            #pragma unroll
            for (int t = 0; t < 4; t++) {
                float4 cc = c4[m * 128 + lane + 32 * t];
                d += x[t].x * cc.x + x[t].y * cc.y + x[t].z * cc.z + x[t].w * cc.w;
            }
            d = wredsum(d) * rinv;
            cm[m] = fmaxf(cm[m], d);
            if (d > best) { best = d; bi = m; }
        }
        if (lane == 0) { g_assign[i] = bi; g_sval[i] = best; }
    }
    if (lane == 0) {
        #pragma unroll
        for (int m = 0; m < MEM; m++) atomicMax(&cm_s[m], f2o(cm[m]));
    }
    __syncthreads();
    if (threadIdx.x < MEM) atomicMax(&g_colmax[threadIdx.x], cm_s[threadIdx.x]);
}

// ---------------- main GEMM (tf32 wmma) + fused epilogue ----------------
// out[i][j] = ALPHA * sum_k text[i][k]*W1T[k][j] + text[i][j] + sum_m p[i][m]*ACW2[m][j]
__global__ void __launch_bounds__(256) k_gemm(const float* __restrict__ text,
                                              float* __restrict__ out) {
    extern __shared__ float sm[];
    float* As = sm;           // [128][16]
    float* Bs = sm + 2048;    // [16][64]
    int tid = threadIdx.x;
    int wid = tid >> 5;
    int wr = wid & 3, wc = wid >> 2;
    int row0 = blockIdx.x * 128, col0 = blockIdx.y * 64;

    wmma::fragment<wmma::accumulator, 16, 16, 8, float> acc[2][2];
    #pragma unroll
    for (int i = 0; i < 2; i++)
        #pragma unroll
        for (int j = 0; j < 2; j++) wmma::fill_fragment(acc[i][j], 0.f);

    const float4* t4 = (const float4*)text;
    const float4* w4 = (const float4*)g_W1T;

    for (int k0 = 0; k0 < DIM; k0 += 16) {
        #pragma unroll
        for (int t = 0; t < 2; t++) {
            int id = tid + t * 256;
            int r = id >> 2, c4i = id & 3;
            ((float4*)As)[r * 4 + c4i] = t4[(size_t)(row0 + r) * 128 + (k0 >> 2) + c4i];
        }
        {
            int c = tid >> 4, j4 = tid & 15;
            ((float4*)Bs)[tid] = w4[(size_t)(k0 + c) * 128 + (col0 >> 2) + j4];
        }
        __syncthreads();
        #pragma unroll
        for (int kk = 0; kk < 16; kk += 8) {
            wmma::fragment<wmma::matrix_a, 16, 16, 8, wmma::precision::tf32, wmma::row_major> a[2];
            wmma::fragment<wmma::matrix_b, 16, 16, 8, wmma::precision::tf32, wmma::row_major> b[2];
            #pragma unroll
            for (int i = 0; i < 2; i++) {
                wmma::load_matrix_sync(a[i], As + (wr * 32 + i * 16) * 16 + kk, 16);
                #pragma unroll
                for (int t = 0; t < a[i].num_elements; t++)
                    a[i].x[t] = wmma::__float_to_tf32(a[i].x[t]);
            }
            #pragma unroll
            for (int j = 0; j < 2; j++) {
                wmma::load_matrix_sync(b[j], Bs + kk * 64 + wc * 32 + j * 16, 64);
                #pragma unroll
                for (int t = 0; t < b[j].num_elements; t++)
                    b[j].x[t] = wmma::__float_to_tf32(b[j].x[t]);
            }
            #pragma unroll
            for (int i = 0; i < 2; i++)
                #pragma unroll
                for (int j = 0; j < 2; j++)
                    wmma::mma_sync(acc[i][j], a[i], b[j], acc[i][j]);
        }
        __syncthreads();
    }

    // epilogue (smem reused)
    float* Cs  = sm;                  // [128][66]
    float* Ps  = sm + 8448;           // [128][26]
    float* Acs = sm + 8448 + 3328;    // [25][64]
    #pragma unroll
    for (int i = 0; i < 2; i++)
        #pragma unroll
        for (int j = 0; j < 2; j++)
            wmma::store_matrix_sync(Cs + (wr * 32 + i * 16) * 66 + wc * 32 + j * 16,
                                    acc[i][j], 66, wmma::mem_row_major);
    for (int id = tid; id < 128 * MEM; id += 256) {
        int r = id / MEM, m = id - r * MEM;
        Ps[r * 26 + m] = g_p[(size_t)(row0 + r) * MEM + m];
    }
    for (int id = tid; id < MEM * 64; id += 256) {
        int m = id >> 6, c = id & 63;
        Acs[id] = g_ACW2[m * DIM + col0 + c];
    }
    __syncthreads();

    int c = tid & 63, rq = tid >> 6;
    float acw[MEM];
    #pragma unroll
    for (int m = 0; m < MEM; m++) acw[m] = Acs[m * 64 + c];
    for (int i = 0; i < 32; i++) {
        int r = rq * 32 + i;
        float v = ALPHA * Cs[r * 66 + c] + text[(size_t)(row0 + r) * DIM + col0 + c];
        #pragma unroll
        for (int m = 0; m < MEM; m++) v += Ps[r * 26 + m] * acw[m];
        out[(size_t)(row0 + r) * DIM + col0 + c] = v;
    }
}

// ---------------- loss partials: mean |normalize(text_fine) - text| ----------------
__global__ void k_loss(const float* __restrict__ out, const float* __restrict__ text) {
    __shared__ float ws[8];
    int lane = threadIdx.x & 31, wid = threadIdx.x >> 5;
    int gw = blockIdx.x * 8 + wid;
    const float4* o4 = (const float4*)out;
    const float4* t4 = (const float4*)text;
    float accum = 0.f;
    for (int i = gw; i < N_TOK; i += 8192) {
        float4 tf[4]; float ss = 0.f;
        #pragma unroll
        for (int t = 0; t < 4; t++) {
            tf[t] = o4[(size_t)i * 128 + lane + 32 * t];
            ss += tf[t].x * tf[t].x + tf[t].y * tf[t].y + tf[t].z * tf[t].z + tf[t].w * tf[t].w;
        }
        ss = wredsum(ss);
        float inv = 1.f / fmaxf(sqrtf(ss), 1e-12f);
        float sa = 0.f;
        #pragma unroll
        for (int t = 0; t < 4; t++) {
            float4 x = t4[(size_t)i * 128 + lane + 32 * t];
            sa += fabsf(tf[t].x * inv - x.x) + fabsf(tf[t].y * inv - x.y) +
                  fabsf(tf[t].z * inv - x.z) + fabsf(tf[t].w * inv - x.w);
        }
        sa = wredsum(sa);
        accum += sa;
    }
    if (lane == 0) ws[wid] = accum;
    __syncthreads();
    if (threadIdx.x == 0) {
        float s = 0.f;
        #pragma unroll
        for (int w = 0; w < 8; w++) s += ws[w];
        g_losspart[blockIdx.x] = s;
    }
}

__global__ void k_loss2(float* __restrict__ out) {
    __shared__ float sh[256];
    int tid = threadIdx.x;
    float s = 0.f;
    for (int id = tid; id < 1024; id += 256) s += g_losspart[id];
    sh[tid] = s;
    __syncthreads();
    for (int off = 128; off > 0; off >>= 1) {
        if (tid < off) sh[tid] += sh[tid + off];
        __syncthreads();
    }
    if (tid == 0) out[(size_t)N_TOK * DIM] = sh[0] * (1.0f / 67108864.0f);
}

// ---------------- scatter: per-block seg/cnt partials ----------------
__global__ void k_scatter(const float* __restrict__ img) {
    extern __shared__ float seg[];         // 12800 seg + 25 cnt
    float* cnts = seg + MEM * DIM;
    __shared__ float cm_s[MEM];
    if (threadIdx.x < MEM) cm_s[threadIdx.x] = o2f(g_colmax[threadIdx.x]);
    for (int id = threadIdx.x; id < MEM * DIM + MEM; id += blockDim.x) seg[id] = 0.f;
    __syncthreads();
    int lane = threadIdx.x & 31, wid = threadIdx.x >> 5;
    int b = blockIdx.x;
    int gw = b * 16 + wid;
    for (int i = gw; i < N_TOK; i += 148 * 16) {
        int a = g_assign[i];
        float w = expf(g_sval[i] - cm_s[a]) * g_rinv[i];
        const float4* r4 = (const float4*)(img + (size_t)i * DIM);
        #pragma unroll
        for (int t = 0; t < 4; t++) {
            float4 v = r4[lane + 32 * t];
            int base = a * DIM + (lane + 32 * t) * 4;
            atomicAdd(&seg[base + 0], w * v.x);
            atomicAdd(&seg[base + 1], w * v.y);
            atomicAdd(&seg[base + 2], w * v.z);
            atomicAdd(&seg[base + 3], w * v.w);
        }
        if (lane == 0) atomicAdd(&cnts[a], 1.0f);
    }
    __syncthreads();
    for (int id = threadIdx.x; id < MEM * DIM; id += blockDim.x)
        g_segp[(size_t)b * (MEM * DIM) + id] = seg[id];
    if (threadIdx.x < MEM) g_cntp[b * MEM + threadIdx.x] = cnts[threadIdx.x];
}

// ---------------- cache EMA update + normalize ----------------
__global__ void k_update(const float* __restrict__ cache, float* __restrict__ out) {
    int m = blockIdx.x, d = threadIdx.x;    // 512 threads
    float cnt = 0.f;
    for (int b = 0; b < 148; b++) cnt += g_cntp[b * MEM + m];
    float s = 0.f;
    for (int b = 0; b < 148; b++) s += g_segp[(size_t)b * (MEM * DIM) + m * DIM + d];
    float cv = cache[m * DIM + d];
    float u = (cnt > 0.f) ? (MOM * cv + (1.f - MOM) * s) : cv;
    float v = u * u;
    v = wredsum(v);
    __shared__ float red[16];
    __shared__ float tot;
    if ((threadIdx.x & 31) == 0) red[threadIdx.x >> 5] = v;
    __syncthreads();
    if (threadIdx.x < 32) {
        float t = (threadIdx.x < 16) ? red[threadIdx.x] : 0.f;
        t = wredsum(t);
        if (threadIdx.x == 0) tot = t;
    }
    __syncthreads();
    float inv = 1.f / fmaxf(sqrtf(tot), 1e-12f);
    out[(size_t)N_TOK * DIM + 1 + m * DIM + d] = u * inv;
}

// ---------------- launch ----------------
extern "C" void kernel_launch(void* const* d_in, const int* in_sizes, int n_in,
                              void* d_out, int out_size) {
    const float* text  = (const float*)d_in[0];
    const float* img   = (const float*)d_in[1];
    const float* W     = (const float*)d_in[2];
    const float* cache = (const float*)d_in[3];
    float* out = (float*)d_out;

    cudaFuncSetAttribute(k_text_attn, cudaFuncAttributeMaxDynamicSharedMemorySize, 51200);
    cudaFuncSetAttribute(k_img_attn,  cudaFuncAttributeMaxDynamicSharedMemorySize, 51200);
    cudaFuncSetAttribute(k_gemm,      cudaFuncAttributeMaxDynamicSharedMemorySize, 53504);
    cudaFuncSetAttribute(k_scatter,   cudaFuncAttributeMaxDynamicSharedMemorySize, 51300);

    k_init<<<1, 32>>>();
    k_transpose<<<dim3(16, 16), dim3(32, 8)>>>(W);
    k_acw2<<<MEM, 256>>>(W, cache);
    k_text_attn<<<1024, 256, 51200>>>(text, cache);
    k_gemm<<<dim3(1024, 8), 256, 53504>>>(text, out);
    k_loss<<<1024, 256>>>(out, text);
    k_loss2<<<1, 256>>>(out);
    k_img_attn<<<1024, 256, 51200>>>(img, cache);
    k_scatter<<<148, 512, 51300>>>(img);
    k_update<<<MEM, 512>>>(cache, out);
}

// round 4
// speedup vs baseline: 1.4750x; 1.4750x over previous
#include <cuda_runtime.h>
#include <cuda_bf16.h>
#include <mma.h>

#define N_TOK 131072
#define DIM   512
#define MEM   25
#define ALPHA 0.2f
#define MOM   0.8f

using namespace nvcuda;

// ---------------- scratch (device globals; no allocation) ----------------
__device__ __nv_bfloat16 g_Bbig[544 * 512];     // [alpha*W1^T ; alpha*cache@W2^T ; 0] bf16
__device__ __nv_bfloat16 g_cacheT[512 * 32];    // cache^T bf16, padded to 32 slots
__device__ float    g_ACW2[MEM * DIM];          // ALPHA * cache @ W2^T (fp32)
__device__ int      g_assign[N_TOK];
__device__ float    g_sval[N_TOK];
__device__ float    g_rinv[N_TOK];
__device__ unsigned g_colmax[MEM];
__device__ float    g_segp[128 * 32 * 512];     // per-block scatter partials
__device__ float    g_cntp[128 * 32];
__device__ float    g_losspart[1024];

__device__ __forceinline__ unsigned f2o(float f) {
    unsigned u = __float_as_uint(f);
    return (u & 0x80000000u) ? ~u : (u | 0x80000000u);
}
__device__ __forceinline__ float o2f(unsigned u) {
    return __uint_as_float((u & 0x80000000u) ? (u & 0x7FFFFFFFu) : ~u);
}
__device__ __forceinline__ float wredsum(float v) {
    v += __shfl_xor_sync(0xffffffffu, v, 16);
    v += __shfl_xor_sync(0xffffffffu, v, 8);
    v += __shfl_xor_sync(0xffffffffu, v, 4);
    v += __shfl_xor_sync(0xffffffffu, v, 2);
    v += __shfl_xor_sync(0xffffffffu, v, 1);
    return v;
}
__device__ __forceinline__ float wredmax(float v) {
    v = fmaxf(v, __shfl_xor_sync(0xffffffffu, v, 16));
    v = fmaxf(v, __shfl_xor_sync(0xffffffffu, v, 8));
    v = fmaxf(v, __shfl_xor_sync(0xffffffffu, v, 4));
    v = fmaxf(v, __shfl_xor_sync(0xffffffffu, v, 2));
    v = fmaxf(v, __shfl_xor_sync(0xffffffffu, v, 1));
    return v;
}

// ---------------- init ----------------
__global__ void k_init() {
    if (threadIdx.x < MEM) g_colmax[threadIdx.x] = 0u;
}

// ---------------- ACW2[m][o] = ALPHA * sum_k cache[m][k] * W[o][512+k] ----------------
__global__ void k_acw2(const float* __restrict__ W, const float* __restrict__ cache) {
    __shared__ float cs[DIM];
    int m = blockIdx.x;
    for (int id = threadIdx.x; id < DIM; id += blockDim.x) cs[id] = cache[m * DIM + id];
    __syncthreads();
    int lane = threadIdx.x & 31, wid = threadIdx.x >> 5;
    for (int j = wid * 64; j < wid * 64 + 64; j++) {
        float d = 0.f;
        #pragma unroll
        for (int t = 0; t < 16; t++) {
            int k = lane + 32 * t;
            d += cs[k] * W[(size_t)j * 1024 + 512 + k];
        }
        d = wredsum(d);
        if (lane == 0) g_ACW2[m * DIM + j] = ALPHA * d;
    }
}

// ---------------- Bbig build: rows 0..511 = ALPHA*W1^T, 512..536 = ACW2, rest 0 ----------------
__global__ void k_prepB(const float* __restrict__ W) {
    int id = blockIdx.x * 256 + threadIdx.x;
    if (id >= 544 * 512) return;
    int r = id >> 9, o = id & 511;
    float v;
    if (r < 512)            v = ALPHA * W[(size_t)o * 1024 + r];
    else if (r < 512 + MEM) v = g_ACW2[(r - 512) * 512 + o];
    else                    v = 0.f;
    g_Bbig[id] = __float2bfloat16(v);
}

__global__ void k_prepC(const float* __restrict__ cache) {
    int id = blockIdx.x * 256 + threadIdx.x;
    if (id >= 512 * 32) return;
    int k = id >> 5, m = id & 31;
    g_cacheT[id] = __float2bfloat16(m < MEM ? cache[m * DIM + k] : 0.f);
}

// ---------------- fused: norm + score MMA + softmax + [text|p]@Bbig + residual ----------------
// smem: A bf16 [128][552] (text cols 0..511, p cols 512..536, zero 537..551)   141312 B
//       B region (69632 B): Bs bf16 [544][64] | {Ct bf16[512][32], Ssm f32[128][36]} | Cs f32[128][68]
//       rowss f32[128]
__global__ void __launch_bounds__(256) k_fused(const float* __restrict__ text,
                                               float* __restrict__ out) {
    extern __shared__ unsigned char smem_raw[];
    __nv_bfloat16* A  = (__nv_bfloat16*)smem_raw;
    unsigned char* Br = smem_raw + 141312;
    __nv_bfloat16* Bs = (__nv_bfloat16*)Br;
    __nv_bfloat16* Ct = (__nv_bfloat16*)Br;
    float* Ssm  = (float*)(Br + 32768);
    float* Cs   = (float*)Br;
    float* rowss = (float*)(smem_raw + 141312 + 69632);

    int tid = threadIdx.x, lane = tid & 31, wid = tid >> 5;
    int row0 = blockIdx.x * 128;
    const float4* t4 = (const float4*)text;

    if (tid < 128) rowss[tid] = 0.f;
    __syncthreads();

    // stage 1: load text fp32 -> bf16 tile + row sumsq
    for (int it = 0; it < 64; it++) {
        int id = it * 256 + tid;
        int r = id >> 7, c = id & 127;
        float4 v = t4[(size_t)(row0 + r) * 128 + c];
        float ss = v.x * v.x + v.y * v.y + v.z * v.z + v.w * v.w;
        ss = wredsum(ss);
        if (lane == 0) atomicAdd(&rowss[r], ss);
        __nv_bfloat162* dst = (__nv_bfloat162*)(A + r * 552 + c * 4);
        dst[0] = __floats2bfloat162_rn(v.x, v.y);
        dst[1] = __floats2bfloat162_rn(v.z, v.w);
    }
    for (int id = tid; id < 128 * 40; id += 256) {
        int r = id / 40, c = 512 + id % 40;
        A[r * 552 + c] = __float2bfloat16(0.f);
    }
    // load cacheT bf16
    {
        const float4* src = (const float4*)g_cacheT;
        float4* dst = (float4*)Ct;
        for (int id = tid; id < 2048; id += 256) dst[id] = src[id];
    }
    __syncthreads();

    // stage 2: score MMA  S[128x32] = A(text) @ cacheT   (warp w -> rows 16w..16w+15)
    {
        wmma::fragment<wmma::accumulator, 16, 16, 16, float> sacc[2];
        wmma::fill_fragment(sacc[0], 0.f);
        wmma::fill_fragment(sacc[1], 0.f);
        for (int k0 = 0; k0 < 512; k0 += 16) {
            wmma::fragment<wmma::matrix_a, 16, 16, 16, __nv_bfloat16, wmma::row_major> af;
            wmma::load_matrix_sync(af, A + (wid * 16) * 552 + k0, 552);
            #pragma unroll
            for (int j = 0; j < 2; j++) {
                wmma::fragment<wmma::matrix_b, 16, 16, 16, __nv_bfloat16, wmma::row_major> bf;
                wmma::load_matrix_sync(bf, Ct + k0 * 32 + j * 16, 32);
                wmma::mma_sync(sacc[j], af, bf, sacc[j]);
            }
        }
        wmma::store_matrix_sync(Ssm + (wid * 16) * 36, sacc[0], 36, wmma::mem_row_major);
        wmma::store_matrix_sync(Ssm + (wid * 16) * 36 + 16, sacc[1], 36, wmma::mem_row_major);
    }
    __syncthreads();

    // stage 3: softmax -> p into A cols 512..536
    for (int rr = 0; rr < 16; rr++) {
        int r = wid * 16 + rr;
        float rinv = 1.f / fmaxf(sqrtf(rowss[r]), 1e-12f);
        float s = (lane < MEM) ? Ssm[r * 36 + lane] * rinv : -1e30f;
        float mx = wredmax(s);
        float e = (lane < MEM) ? expf(s - mx) : 0.f;
        float sum = wredsum(e);
        if (lane < MEM) A[r * 552 + 512 + lane] = __float2bfloat16(e / sum);
    }
    __syncthreads();

    // stage 4: per 64-col chunk: out = A @ Bbig_chunk + text
    int wr = wid & 3, wc = wid >> 2;
    for (int cb = 0; cb < 8; cb++) {
        int col0 = cb * 64;
        for (int id = tid; id < 544 * 8; id += 256) {
            int r = id >> 3, g = id & 7;
            ((float4*)Bs)[r * 8 + g] = ((const float4*)g_Bbig)[r * 64 + (col0 >> 3) + g];
        }
        __syncthreads();
        wmma::fragment<wmma::accumulator, 16, 16, 16, float> acc[2][2];
        #pragma unroll
        for (int i = 0; i < 2; i++)
            #pragma unroll
            for (int j = 0; j < 2; j++) wmma::fill_fragment(acc[i][j], 0.f);
        for (int k0 = 0; k0 < 544; k0 += 16) {
            wmma::fragment<wmma::matrix_a, 16, 16, 16, __nv_bfloat16, wmma::row_major> af[2];
            wmma::fragment<wmma::matrix_b, 16, 16, 16, __nv_bfloat16, wmma::row_major> bf[2];
            #pragma unroll
            for (int i = 0; i < 2; i++)
                wmma::load_matrix_sync(af[i], A + (wr * 32 + i * 16) * 552 + k0, 552);
            #pragma unroll
            for (int j = 0; j < 2; j++)
                wmma::load_matrix_sync(bf[j], Bs + k0 * 64 + wc * 32 + j * 16, 64);
            #pragma unroll
            for (int i = 0; i < 2; i++)
                #pragma unroll
                for (int j = 0; j < 2; j++)
                    wmma::mma_sync(acc[i][j], af[i], bf[j], acc[i][j]);
        }
        __syncthreads();   // all warps done reading Bs before Cs overwrites it
        #pragma unroll
        for (int i = 0; i < 2; i++)
            #pragma unroll
            for (int j = 0; j < 2; j++)
                wmma::store_matrix_sync(Cs + (wr * 32 + i * 16) * 68 + wc * 32 + j * 16,
                                        acc[i][j], 68, wmma::mem_row_major);
        __syncthreads();
        for (int it = 0; it < 8; it++) {
            int id = it * 256 + tid;
            int r = id >> 4, q = id & 15;
            float4 v = *((float4*)&Cs[r * 68 + q * 4]);
            float4 t = t4[(size_t)(row0 + r) * 128 + (col0 >> 2) + q];
            v.x += t.x; v.y += t.y; v.z += t.z; v.w += t.w;
            ((float4*)out)[(size_t)(row0 + r) * 128 + (col0 >> 2) + q] = v;
        }
        __syncthreads();
    }
}

// ---------------- loss partials ----------------
__global__ void k_loss(const float* __restrict__ out, const float* __restrict__ text) {
    __shared__ float ws[8];
    int lane = threadIdx.x & 31, wid = threadIdx.x >> 5;
    int gw = blockIdx.x * 8 + wid;
    const float4* o4 = (const float4*)out;
    const float4* t4 = (const float4*)text;
    float accum = 0.f;
    for (int i = gw; i < N_TOK; i += 8192) {
        float4 tf[4]; float ss = 0.f;
        #pragma unroll
        for (int t = 0; t < 4; t++) {
            tf[t] = o4[(size_t)i * 128 + lane + 32 * t];
            ss += tf[t].x * tf[t].x + tf[t].y * tf[t].y + tf[t].z * tf[t].z + tf[t].w * tf[t].w;
        }
        ss = wredsum(ss);
        float inv = 1.f / fmaxf(sqrtf(ss), 1e-12f);
        float sa = 0.f;
        #pragma unroll
        for (int t = 0; t < 4; t++) {
            float4 x = t4[(size_t)i * 128 + lane + 32 * t];
            sa += fabsf(tf[t].x * inv - x.x) + fabsf(tf[t].y * inv - x.y) +
                  fabsf(tf[t].z * inv - x.z) + fabsf(tf[t].w * inv - x.w);
        }
        accum += wredsum(sa);
    }
    if (lane == 0) ws[wid] = accum;
    __syncthreads();
    if (threadIdx.x == 0) {
        float s = 0.f;
        #pragma unroll
        for (int w = 0; w < 8; w++) s += ws[w];
        g_losspart[blockIdx.x] = s;
    }
}

__global__ void k_loss2(float* __restrict__ out) {
    __shared__ float sh[256];
    int tid = threadIdx.x;
    float s = 0.f;
    for (int id = tid; id < 1024; id += 256) s += g_losspart[id];
    sh[tid] = s;
    __syncthreads();
    for (int off = 128; off > 0; off >>= 1) {
        if (tid < off) sh[tid] += sh[tid + off];
        __syncthreads();
    }
    if (tid == 0) out[(size_t)N_TOK * DIM] = sh[0] * (1.0f / 67108864.0f);
}

// ---------------- image attention (fp32, 4-token register blocking) ----------------
__global__ void k_img_attn(const float* __restrict__ img, const float* __restrict__ cache) {
    extern __shared__ float cs[];
    __shared__ unsigned cm_s[MEM];
    if (threadIdx.x < MEM) cm_s[threadIdx.x] = 0u;
    for (int i = threadIdx.x; i < MEM * DIM / 4; i += blockDim.x)
        ((float4*)cs)[i] = ((const float4*)cache)[i];
    __syncthreads();
    int lane = threadIdx.x & 31, wid = threadIdx.x >> 5;
    int gw = blockIdx.x * 8 + wid;
    int nw = gridDim.x * 8;
    const float4* c4 = (const float4*)cs;
    float cm[MEM];
    #pragma unroll
    for (int m = 0; m < MEM; m++) cm[m] = -1e30f;
    for (int i0 = gw * 4; i0 < N_TOK; i0 += nw * 4) {
        float4 x[4][4]; float rv[4];
        #pragma unroll
        for (int tt = 0; tt < 4; tt++) {
            const float4* r4 = (const float4*)(img + (size_t)(i0 + tt) * DIM);
            float ss = 0.f;
            #pragma unroll
            for (int t = 0; t < 4; t++) {
                x[tt][t] = r4[lane + 32 * t];
                ss += x[tt][t].x * x[tt][t].x + x[tt][t].y * x[tt][t].y +
                      x[tt][t].z * x[tt][t].z + x[tt][t].w * x[tt][t].w;
            }
            ss = wredsum(ss);
            rv[tt] = rsqrtf(ss);
        }
        if (lane == 0) {
            g_rinv[i0] = rv[0]; g_rinv[i0 + 1] = rv[1];
            g_rinv[i0 + 2] = rv[2]; g_rinv[i0 + 3] = rv[3];
        }
        float best[4] = {-1e30f, -1e30f, -1e30f, -1e30f};
        int bi[4] = {0, 0, 0, 0};
        #pragma unroll
        for (int m = 0; m < MEM; m++) {
            float d0 = 0.f, d1 = 0.f, d2 = 0.f, d3 = 0.f;
            #pragma unroll
            for (int t = 0; t < 4; t++) {
                float4 cc = c4[m * 128 + lane + 32 * t];
                d0 += x[0][t].x * cc.x + x[0][t].y * cc.y + x[0][t].z * cc.z + x[0][t].w * cc.w;
                d1 += x[1][t].x * cc.x + x[1][t].y * cc.y + x[1][t].z * cc.z + x[1][t].w * cc.w;
                d2 += x[2][t].x * cc.x + x[2][t].y * cc.y + x[2][t].z * cc.z + x[2][t].w * cc.w;
                d3 += x[3][t].x * cc.x + x[3][t].y * cc.y + x[3][t].z * cc.z + x[3][t].w * cc.w;
            }
            d0 = wredsum(d0) * rv[0];
            d1 = wredsum(d1) * rv[1];
            d2 = wredsum(d2) * rv[2];
            d3 = wredsum(d3) * rv[3];
            cm[m] = fmaxf(cm[m], fmaxf(fmaxf(d0, d1), fmaxf(d2, d3)));
            if (d0 > best[0]) { best[0] = d0; bi[0] = m; }
            if (d1 > best[1]) { best[1] = d1; bi[1] = m; }
            if (d2 > best[2]) { best[2] = d2; bi[2] = m; }
            if (d3 > best[3]) { best[3] = d3; bi[3] = m; }
        }
        if (lane == 0) {
            g_assign[i0] = bi[0]; g_sval[i0] = best[0];
            g_assign[i0 + 1] = bi[1]; g_sval[i0 + 1] = best[1];
            g_assign[i0 + 2] = bi[2]; g_sval[i0 + 2] = best[2];
            g_assign[i0 + 3] = bi[3]; g_sval[i0 + 3] = best[3];
        }
    }
    if (lane == 0) {
        #pragma unroll
        for (int m = 0; m < MEM; m++) atomicMax(&cm_s[m], f2o(cm[m]));
    }
    __syncthreads();
    if (threadIdx.x < MEM) atomicMax(&g_colmax[threadIdx.x], cm_s[threadIdx.x]);
}

// ---------------- scatter as tf32 MMA: seg_part = A(w,onehot) @ img ----------------
// smem: Bimg f32 [64][520] (133120 B) + Aw f32 [32][72] (9216 B)
__global__ void __launch_bounds__(256) k_scatter(const float* __restrict__ img) {
    extern __shared__ unsigned char sraw[];
    float* Bimg = (float*)sraw;
    float* Aw   = (float*)(sraw + 64 * 520 * 4);
    __shared__ float cnts[32];
    __shared__ float cm_s[MEM];
    int tid = threadIdx.x, wid = tid >> 5;
    if (tid < MEM) cm_s[tid] = o2f(g_colmax[tid]);
    if (tid < 32) cnts[tid] = 0.f;

    wmma::fragment<wmma::accumulator, 16, 16, 8, float> acc[2][4];
    #pragma unroll
    for (int i = 0; i < 2; i++)
        #pragma unroll
        for (int j = 0; j < 4; j++) wmma::fill_fragment(acc[i][j], 0.f);
    __syncthreads();

    const float4* i4 = (const float4*)img;
    for (int tile = 0; tile < 16; tile++) {
        int base = blockIdx.x * 1024 + tile * 64;
        for (int id = tid; id < 32 * 72; id += 256) Aw[id] = 0.f;
        for (int id = tid; id < 64 * 128; id += 256) {
            int r = id >> 7, c = id & 127;
            *((float4*)&Bimg[r * 520 + c * 4]) = i4[(size_t)(base + r) * 128 + c];
        }
        __syncthreads();
        if (tid < 64) {
            int i = base + tid;
            int a = g_assign[i];
            float w = expf(g_sval[i] - cm_s[a]) * g_rinv[i];
            Aw[a * 72 + tid] = w;
            atomicAdd(&cnts[a], 1.f);
        }
        __syncthreads();
        for (int ks = 0; ks < 8; ks++) {
            int k0 = ks * 8;
            wmma::fragment<wmma::matrix_a, 16, 16, 8, wmma::precision::tf32, wmma::row_major> af[2];
            wmma::fragment<wmma::matrix_b, 16, 16, 8, wmma::precision::tf32, wmma::row_major> bf[4];
            #pragma unroll
            for (int i = 0; i < 2; i++) {
                wmma::load_matrix_sync(af[i], Aw + (i * 16) * 72 + k0, 72);
                #pragma unroll
                for (int t = 0; t < af[i].num_elements; t++)
                    af[i].x[t] = wmma::__float_to_tf32(af[i].x[t]);
            }
            #pragma unroll
            for (int j = 0; j < 4; j++) {
                wmma::load_matrix_sync(bf[j], Bimg + k0 * 520 + wid * 64 + j * 16, 520);
                #pragma unroll
                for (int t = 0; t < bf[j].num_elements; t++)
                    bf[j].x[t] = wmma::__float_to_tf32(bf[j].x[t]);
            }
            #pragma unroll
            for (int i = 0; i < 2; i++)
                #pragma unroll
                for (int j = 0; j < 4; j++)
                    wmma::mma_sync(acc[i][j], af[i], bf[j], acc[i][j]);
        }
        __syncthreads();
    }
    #pragma unroll
    for (int i = 0; i < 2; i++)
        #pragma unroll
        for (int j = 0; j < 4; j++)
            wmma::store_matrix_sync(g_segp + (size_t)blockIdx.x * 16384 + (i * 16) * 512 +
                                    wid * 64 + j * 16, acc[i][j], 512, wmma::mem_row_major);
    if (tid < 32) g_cntp[blockIdx.x * 32 + tid] = cnts[tid];
}

// ---------------- cache EMA update + normalize ----------------
__global__ void k_update(const float* __restrict__ cache, float* __restrict__ out) {
    int m = blockIdx.x, d = threadIdx.x;
    float cnt = 0.f;
    for (int b = 0; b < 128; b++) cnt += g_cntp[b * 32 + m];
    float s = 0.f;
    for (int b = 0; b < 128; b++) s += g_segp[(size_t)b * 16384 + m * 512 + d];
    float cv = cache[m * DIM + d];
    float u = (cnt > 0.f) ? (MOM * cv + (1.f - MOM) * s) : cv;
    float v = u * u;
    v = wredsum(v);
    __shared__ float red[16];
    __shared__ float tot;
    if ((threadIdx.x & 31) == 0) red[threadIdx.x >> 5] = v;
    __syncthreads();
    if (threadIdx.x < 32) {
        float t = (threadIdx.x < 16) ? red[threadIdx.x] : 0.f;
        t = wredsum(t);
        if (threadIdx.x == 0) tot = t;
    }
    __syncthreads();
    float inv = 1.f / fmaxf(sqrtf(tot), 1e-12f);
    out[(size_t)N_TOK * DIM + 1 + m * DIM + d] = u * inv;
}

// ---------------- launch ----------------
extern "C" void kernel_launch(void* const* d_in, const int* in_sizes, int n_in,
                              void* d_out, int out_size) {
    const float* text  = (const float*)d_in[0];
    const float* img   = (const float*)d_in[1];
    const float* W     = (const float*)d_in[2];
    const float* cache = (const float*)d_in[3];
    float* out = (float*)d_out;

    const int FUSED_SMEM   = 141312 + 69632 + 512;       // 211456
    const int SCATTER_SMEM = 64 * 520 * 4 + 32 * 72 * 4; // 142336

    cudaFuncSetAttribute(k_fused,    cudaFuncAttributeMaxDynamicSharedMemorySize, FUSED_SMEM);
    cudaFuncSetAttribute(k_img_attn, cudaFuncAttributeMaxDynamicSharedMemorySize, 51200);
    cudaFuncSetAttribute(k_scatter,  cudaFuncAttributeMaxDynamicSharedMemorySize, SCATTER_SMEM);

    k_init<<<1, 32>>>();
    k_acw2<<<MEM, 256>>>(W, cache);
    k_prepB<<<(544 * 512 + 255) / 256, 256>>>(W);
    k_prepC<<<(512 * 32 + 255) / 256, 256>>>(cache);
    k_fused<<<1024, 256, FUSED_SMEM>>>(text, out);
    k_loss<<<1024, 256>>>(out, text);
    k_loss2<<<1, 256>>>(out);
    k_img_attn<<<512, 256, 51200>>>(img, cache);
    k_scatter<<<128, 256, SCATTER_SMEM>>>(img);
    k_update<<<MEM, 512>>>(cache, out);
}